// round 7
// baseline (speedup 1.0000x reference)
#include <cuda_runtime.h>
#include <cstdint>

#define BEV_H 128
#define BEV_W 128
#define HW_ (BEV_H * BEV_W)
#define C_MID 80
#define C_OUT 128
#define B_ 4
#define NP_ 200000
#define TOTAL_PTS (B_ * NP_)

#define WARPS_PER_CTA 4
#define TILES_PER_WARP 5
#define POINT_GRID (TOTAL_PTS / (32 * WARPS_PER_CTA * TILES_PER_WARP))  // 1250

#define BEV_TILES (B_ * HW_ / 16)
#define BEV_TPW 4
#define BEV_GRID (BEV_TILES / (4 * BEV_TPW))   // 256

// Scratch (zero-init at load; bev kernel re-zeroes what it consumes).
__device__ float g_sums[(size_t)B_ * HW_ * C_MID];  // ~21 MB
__device__ float g_cnt[B_ * HW_];

// ---------------------------------------------------------------------------
// helpers
// ---------------------------------------------------------------------------
__device__ __forceinline__ uint32_t f2tf32(float x) {
    uint32_t u;
    asm("cvt.rna.tf32.f32 %0, %1;" : "=r"(u) : "f"(x));
    return u;
}
__device__ __forceinline__ uint32_t packh2(float lo, float hi) {
    uint32_t r;  // cvt.f16x2: first src -> high half, second -> low half
    asm("cvt.rn.f16x2.f32 %0, %1, %2;" : "=r"(r) : "f"(hi), "f"(lo));
    return r;
}
// m16n8k16 row.col f32.f16.f16.f32
__device__ __forceinline__ void mma_f16(float* c, const uint32_t* a,
                                        uint32_t b0, uint32_t b1) {
    asm("mma.sync.aligned.m16n8k16.row.col.f32.f16.f16.f32 "
        "{%0,%1,%2,%3}, {%4,%5,%6,%7}, {%8,%9}, {%0,%1,%2,%3};"
        : "+f"(c[0]), "+f"(c[1]), "+f"(c[2]), "+f"(c[3])
        : "r"(a[0]), "r"(a[1]), "r"(a[2]), "r"(a[3]), "r"(b0), "r"(b1));
}
// m16n8k8 tf32 (bev kernel)
__device__ __forceinline__ void mma_tf32(float* c, const uint32_t* a,
                                         uint32_t b0, uint32_t b1) {
    asm("mma.sync.aligned.m16n8k8.row.col.f32.tf32.tf32.f32 "
        "{%0,%1,%2,%3}, {%4,%5,%6,%7}, {%8,%9}, {%0,%1,%2,%3};"
        : "+f"(c[0]), "+f"(c[1]), "+f"(c[2]), "+f"(c[3])
        : "r"(a[0]), "r"(a[1]), "r"(a[2]), "r"(a[3]), "r"(b0), "r"(b1));
}

// Dynamic smem layout (bytes)
#define SM_W2F   0                      // 5*10*32*2 u32 = 12800
#define SM_BUF   12800                  // 4 warps * 32*80*4 = 40960
#define SM_W1    53760                  // 320 f
#define SM_B1    55040                  // 80 f
#define SM_B2    55360                  // 80 f
#define SM_TOTAL 55680

// ---------------------------------------------------------------------------
// Kernel 1: per-point MLP via fp16 tensor cores + contiguous scatter.
// ---------------------------------------------------------------------------
__global__ __launch_bounds__(128, 4)
void point_mma_kernel(const float4* __restrict__ pts,
                      const float* __restrict__ W1, const float* __restrict__ b1,
                      const float* __restrict__ W2, const float* __restrict__ b2) {
    extern __shared__ __align__(16) char smem[];
    uint32_t* sW2F = (uint32_t*)(smem + SM_W2F);
    float*    sW1  = (float*)(smem + SM_W1);
    float*    sb1  = (float*)(smem + SM_B1);
    float*    sb2  = (float*)(smem + SM_B2);

    const int tid = threadIdx.x;
    const int w = tid >> 5;
    const int lane = tid & 31;
    const int qg = lane >> 2;
    const int tig = lane & 3;
    float* buf = (float*)(smem + SM_BUF) + w * 32 * C_MID;

    for (int i = tid; i < 4 * C_MID; i += 128) sW1[i] = W1[i];
    for (int i = tid; i < C_MID; i += 128) { sb1[i] = b1[i]; sb2[i] = b2[i]; }
    // B fragments (fp16): entry[(ks*10+ns)*32+L][reg] = f16x2 of
    // W2[k0][n], W2[k0+1][n]  with k0 = 16ks + 2tig + 8*reg, n = 8ns + qg
    for (int e = tid; e < 3200; e += 128) {
        int reg = e & 1;
        int L = (e >> 1) & 31;
        int idx = e >> 6;
        int ns = idx % 10, ks = idx / 10;
        int k0 = ks * 16 + 2 * (L & 3) + reg * 8;
        int n = ns * 8 + (L >> 2);
        sW2F[e] = packh2(W2[k0 * C_MID + n], W2[(k0 + 1) * C_MID + n]);
    }
    __syncthreads();

    // Epilogue constants (lanes 0..19 each own 4 channels)
    float4 bias4 = make_float4(0.f, 0.f, 0.f, 0.f);
    if (lane < 20) bias4 = *reinterpret_cast<const float4*>(&sb2[4 * lane]);

    for (int t = 0; t < TILES_PER_WARP; t++) {
        const int tile = (blockIdx.x * WARPS_PER_CTA + w) * TILES_PER_WARP + t;
        const int base = tile * 32;

        // rows qg + 8j
        float4 P[4];
#pragma unroll
        for (int j = 0; j < 4; j++) P[j] = pts[base + qg + 8 * j];

        // This lane owns tile row (qg + 8*tig) for bucket bookkeeping.
        int myg;
        {
            float4 po = P[tig];
            int ixo = (int)floorf((po.x + 50.0f) / 0.78125f);
            int iyo = (int)floorf((po.y + 50.0f) / 0.78125f);
            bool v = (ixo >= 0) & (ixo < BEV_W) & (iyo >= 0) & (iyo < BEV_H);
            int row = qg + 8 * tig;
            myg = v ? ((base + row) / NP_) * HW_ + iyo * BEV_W + ixo : -1;
            if (v) atomicAdd(&g_cnt[myg], 1.0f);
        }

        // Layer 1 -> fp16 A fragments. Per ks: cols 16ks+2tig(+1), +8(+9).
        uint32_t A0[5][4], A1[5][4];
#pragma unroll
        for (int ks = 0; ks < 5; ks++) {
            const int c00 = ks * 16 + 2 * tig;
#pragma unroll
            for (int half = 0; half < 2; half++) {     // cols c00+8*half
                const int ca = c00 + 8 * half, cb = ca + 1;
                float wa0 = sW1[ca], wa1 = sW1[C_MID + ca],
                      wa2 = sW1[2 * C_MID + ca], wa3 = sW1[3 * C_MID + ca], ba = sb1[ca];
                float wb0 = sW1[cb], wb1 = sW1[C_MID + cb],
                      wb2 = sW1[2 * C_MID + cb], wb3 = sW1[3 * C_MID + cb], bb = sb1[cb];
#pragma unroll
                for (int j = 0; j < 4; j++) {          // rows qg + 8j
                    float va = fmaf(P[j].x, wa0, ba);
                    va = fmaf(P[j].y, wa1, va);
                    va = fmaf(P[j].z, wa2, va);
                    va = fmaf(P[j].w, wa3, va);
                    float vb = fmaf(P[j].x, wb0, bb);
                    vb = fmaf(P[j].y, wb1, vb);
                    vb = fmaf(P[j].z, wb2, vb);
                    vb = fmaf(P[j].w, wb3, vb);
                    uint32_t u = packh2(fmaxf(va, 0.0f), fmaxf(vb, 0.0f));
                    if (j < 2) A0[ks][half * 2 + j] = u;       // a0/a1 (half=0), a2/a3 (half=1)
                    else       A1[ks][half * 2 + (j - 2)] = u;
                }
            }
        }

        // MMA + stage results to smem (row-major [pt][channel], stride 80).
#pragma unroll 1
        for (int ns = 0; ns < 10; ns++) {
            float c0[4] = {0.f, 0.f, 0.f, 0.f};
            float c1[4] = {0.f, 0.f, 0.f, 0.f};
#pragma unroll
            for (int ks = 0; ks < 5; ks++) {
                uint2 bf = *reinterpret_cast<const uint2*>(
                    &sW2F[((ks * 10 + ns) * 32 + lane) * 2]);
                mma_f16(c0, A0[ks], bf.x, bf.y);
                mma_f16(c1, A1[ks], bf.x, bf.y);
            }
            const int col = ns * 8 + 2 * tig;
            *reinterpret_cast<float2*>(&buf[qg * C_MID + col])        = make_float2(c0[0], c0[1]);
            *reinterpret_cast<float2*>(&buf[(qg + 8) * C_MID + col])  = make_float2(c0[2], c0[3]);
            *reinterpret_cast<float2*>(&buf[(qg + 16) * C_MID + col]) = make_float2(c1[0], c1[1]);
            *reinterpret_cast<float2*>(&buf[(qg + 24) * C_MID + col]) = make_float2(c1[2], c1[3]);
        }
        __syncwarp();

        // Per-point contiguous scatter: 20 lanes cover the 80 channels.
#pragma unroll 1
        for (int p = 0; p < 32; p++) {
            int gp = __shfl_sync(0xffffffffu, myg, ((p & 7) << 2) | (p >> 3));
            if (gp < 0) continue;
            if (lane < 20) {
                float4 v = *reinterpret_cast<const float4*>(&buf[p * C_MID + 4 * lane]);
                float e0 = fmaxf(v.x + bias4.x, 0.0f);
                float e1 = fmaxf(v.y + bias4.y, 0.0f);
                float e2 = fmaxf(v.z + bias4.z, 0.0f);
                float e3 = fmaxf(v.w + bias4.w, 0.0f);
                asm volatile("red.global.add.v4.f32 [%0], {%1, %2, %3, %4};"
                             :: "l"(&g_sums[(size_t)gp * C_MID + 4 * lane]),
                                "f"(e0), "f"(e1), "f"(e2), "f"(e3) : "memory");
            }
        }
        __syncwarp();
    }
}

// ---------------------------------------------------------------------------
// Kernel 2: mean + 1x1 conv + BN + relu via tensor cores (unchanged, ~22us).
// ---------------------------------------------------------------------------
__global__ __launch_bounds__(128)
void bev_mma_kernel(const float* __restrict__ Wp, const float* __restrict__ bp,
                    const float* __restrict__ gamma, const float* __restrict__ beta,
                    const float* __restrict__ rmean, const float* __restrict__ rvar,
                    float* __restrict__ out) {
    __shared__ uint32_t sWpF[10 * 16 * 32 * 2];  // 40 KB
    __shared__ float sScale[C_OUT];
    __shared__ float sShift[C_OUT];

    const int tid = threadIdx.x;
    const int w = tid >> 5;
    const int lane = tid & 31;
    const int qg = lane >> 2;
    const int tig = lane & 3;

    for (int e = tid; e < 10240; e += 128) {
        int pair = e & 1;
        int L = (e >> 1) & 31;
        int idx = e >> 6;
        int ns = idx & 15, ks = idx >> 4;
        int k = ks * 8 + (L & 3) + pair * 4;
        int n = ns * 8 + (L >> 2);
        sWpF[e] = f2tf32(Wp[k * C_OUT + n]);
    }
    if (tid < C_OUT) {
        float sc = gamma[tid] * rsqrtf(rvar[tid] + 1e-5f);
        sScale[tid] = sc;
        sShift[tid] = beta[tid] + (bp[tid] - rmean[tid]) * sc;
    }
    __syncthreads();

#pragma unroll 1
    for (int t = 0; t < BEV_TPW; t++) {
        const int tile = (blockIdx.x * 4 + w) * BEV_TPW + t;
        const int tb = tile * 16;

        float cnt0 = g_cnt[tb + qg];
        float cnt1 = g_cnt[tb + qg + 8];
        float inv0 = 1.0f / fmaxf(cnt0, 1.0f);
        float inv1 = 1.0f / fmaxf(cnt1, 1.0f);
        const float* p0 = &g_sums[(size_t)(tb + qg) * C_MID];
        const float* p1 = &g_sums[(size_t)(tb + qg + 8) * C_MID];

        uint32_t A[10][4];
#pragma unroll
        for (int ks = 0; ks < 10; ks++) {
            const int c0 = ks * 8 + tig, c1 = c0 + 4;
            A[ks][0] = f2tf32(p0[c0] * inv0);
            A[ks][1] = f2tf32(p1[c0] * inv1);
            A[ks][2] = f2tf32(p0[c1] * inv0);
            A[ks][3] = f2tf32(p1[c1] * inv1);
        }
        __syncwarp();
        float4* zs = reinterpret_cast<float4*>(&g_sums[(size_t)tb * C_MID]);
#pragma unroll
        for (int j = 0; j < 10; j++)
            zs[lane + 32 * j] = make_float4(0.f, 0.f, 0.f, 0.f);
        if (lane < 16) g_cnt[tb + lane] = 0.0f;

        const int b = tb / HW_;
        const int rem = tb % HW_;
        float* outb = out + (size_t)b * C_OUT * HW_ + rem;

#pragma unroll 1
        for (int ns = 0; ns < 16; ns++) {
            float c[4] = {0.f, 0.f, 0.f, 0.f};
#pragma unroll
            for (int ks = 0; ks < 10; ks++) {
                uint2 bf = *reinterpret_cast<const uint2*>(
                    &sWpF[((ks * 16 + ns) * 32 + lane) * 2]);
                mma_tf32(c, A[ks], bf.x, bf.y);
            }
            const int col0 = ns * 8 + 2 * tig;
            float2 sc = *reinterpret_cast<const float2*>(&sScale[col0]);
            float2 sh = *reinterpret_cast<const float2*>(&sShift[col0]);
            outb[(size_t)col0 * HW_ + qg]           = fmaxf(fmaf(c[0], sc.x, sh.x), 0.0f);
            outb[(size_t)(col0 + 1) * HW_ + qg]     = fmaxf(fmaf(c[1], sc.y, sh.y), 0.0f);
            outb[(size_t)col0 * HW_ + qg + 8]       = fmaxf(fmaf(c[2], sc.x, sh.x), 0.0f);
            outb[(size_t)(col0 + 1) * HW_ + qg + 8] = fmaxf(fmaf(c[3], sc.y, sh.y), 0.0f);
        }
        __syncwarp();
    }
}

__global__ void probe_kernel() {}

// ---------------------------------------------------------------------------
extern "C" void kernel_launch(void* const* d_in, const int* in_sizes, int n_in,
                              void* d_out, int out_size) {
    const float4* pts   = (const float4*)d_in[0];
    const float*  W1    = (const float*)d_in[1];
    const float*  b1    = (const float*)d_in[2];
    const float*  W2    = (const float*)d_in[3];
    const float*  b2    = (const float*)d_in[4];
    const float*  Wp    = (const float*)d_in[5];
    const float*  bp    = (const float*)d_in[6];
    const float*  gamma = (const float*)d_in[7];
    const float*  beta  = (const float*)d_in[8];
    const float*  rmean = (const float*)d_in[9];
    const float*  rvar  = (const float*)d_in[10];
    float* out = (float*)d_out;

    cudaFuncSetAttribute(point_mma_kernel,
                         cudaFuncAttributeMaxDynamicSharedMemorySize, SM_TOTAL);
    point_mma_kernel<<<POINT_GRID, 128, SM_TOTAL>>>(pts, W1, b1, W2, b2);
    bev_mma_kernel<<<BEV_GRID, 128>>>(Wp, bp, gamma, beta, rmean, rvar, out);
    probe_kernel<<<1, 1>>>();
}

// round 8
// speedup vs baseline: 1.1238x; 1.1238x over previous
#include <cuda_runtime.h>
#include <cstdint>

#define BEV_H 128
#define BEV_W 128
#define HW_ (BEV_H * BEV_W)
#define C_MID 80
#define C_OUT 128
#define B_ 4
#define NP_ 200000
#define TOTAL_PTS (B_ * NP_)

#define WARPS_PER_CTA 4
#define TILES_PER_WARP 5
#define POINT_GRID (TOTAL_PTS / (32 * WARPS_PER_CTA * TILES_PER_WARP))  // 1250

#define BEV_TILES (B_ * HW_ / 16)
#define BEV_TPW 4
#define BEV_GRID (BEV_TILES / (4 * BEV_TPW))   // 256

// Scratch (zero-init at load; bev kernel re-zeroes what it consumes).
__device__ float g_sums[(size_t)B_ * HW_ * C_MID];  // ~21 MB
__device__ float g_cnt[B_ * HW_];

// ---------------------------------------------------------------------------
// helpers
// ---------------------------------------------------------------------------
__device__ __forceinline__ uint32_t f2tf32(float x) {
    uint32_t u;
    asm("cvt.rna.tf32.f32 %0, %1;" : "=r"(u) : "f"(x));
    return u;
}
__device__ __forceinline__ uint32_t packh2(float lo, float hi) {
    uint32_t r;  // cvt.f16x2: first operand -> high half, second -> low half
    asm("cvt.rn.f16x2.f32 %0, %1, %2;" : "=r"(r) : "f"(hi), "f"(lo));
    return r;
}
// m16n8k16 row.col f32.f16.f16.f32
__device__ __forceinline__ void mma_f16(float* c, const uint32_t* a,
                                        uint32_t b0, uint32_t b1) {
    asm("mma.sync.aligned.m16n8k16.row.col.f32.f16.f16.f32 "
        "{%0,%1,%2,%3}, {%4,%5,%6,%7}, {%8,%9}, {%0,%1,%2,%3};"
        : "+f"(c[0]), "+f"(c[1]), "+f"(c[2]), "+f"(c[3])
        : "r"(a[0]), "r"(a[1]), "r"(a[2]), "r"(a[3]), "r"(b0), "r"(b1));
}
// m16n8k8 tf32 (bev kernel)
__device__ __forceinline__ void mma_tf32(float* c, const uint32_t* a,
                                         uint32_t b0, uint32_t b1) {
    asm("mma.sync.aligned.m16n8k8.row.col.f32.tf32.tf32.f32 "
        "{%0,%1,%2,%3}, {%4,%5,%6,%7}, {%8,%9}, {%0,%1,%2,%3};"
        : "+f"(c[0]), "+f"(c[1]), "+f"(c[2]), "+f"(c[3])
        : "r"(a[0]), "r"(a[1]), "r"(a[2]), "r"(a[3]), "r"(b0), "r"(b1));
}

// ---------------------------------------------------------------------------
// Kernel 1: per-point MLP via fp16 tensor cores (R6 structure, R7 math).
// Warp tile = 32 points. A-fragments built straight out of layer-1 (fp16x2),
// B = W2 staged in exact fp16 b-fragment order. Epilogue: shuffle-exchange,
// red.global.add.v4 scatter directly from C fragments.
// ---------------------------------------------------------------------------
__global__ __launch_bounds__(128, 5)
void point_mma_kernel(const float4* __restrict__ pts,
                      const float* __restrict__ W1, const float* __restrict__ b1,
                      const float* __restrict__ W2, const float* __restrict__ b2) {
    __shared__ uint32_t sW2F[5 * 10 * 32 * 2];   // fp16 b-frags, 12.8 KB
    __shared__ float sW1[4 * C_MID];
    __shared__ float sb1[C_MID];
    __shared__ __align__(16) float sb2[C_MID];
    __shared__ int g_buf[WARPS_PER_CTA][32];

    const int tid = threadIdx.x;
    const int w = tid >> 5;
    const int lane = tid & 31;
    const int qg = lane >> 2;
    const int tig = lane & 3;

    for (int i = tid; i < 4 * C_MID; i += 128) sW1[i] = W1[i];
    for (int i = tid; i < C_MID; i += 128) { sb1[i] = b1[i]; sb2[i] = b2[i]; }
    // fp16 B fragments: entry[(ks*10+ns)*32+L][reg] packs
    // W2[k0][n], W2[k0+1][n], k0 = 16ks + 2*(L&3) + 8*reg, n = 8ns + (L>>2)
    for (int e = tid; e < 3200; e += 128) {
        int reg = e & 1;
        int L = (e >> 1) & 31;
        int idx = e >> 6;
        int ns = idx % 10, ks = idx / 10;
        int k0 = ks * 16 + 2 * (L & 3) + reg * 8;
        int n = ns * 8 + (L >> 2);
        sW2F[e] = packh2(W2[k0 * C_MID + n], W2[(k0 + 1) * C_MID + n]);
    }
    __syncthreads();

    const bool even = (tig & 1) == 0;

    for (int t = 0; t < TILES_PER_WARP; t++) {
        const int tile = (blockIdx.x * WARPS_PER_CTA + w) * TILES_PER_WARP + t;
        const int base = tile * 32;

        float4 P[4];
#pragma unroll
        for (int j = 0; j < 4; j++) P[j] = pts[base + qg + 8 * j];

        {
            float4 po = P[tig];
            int ixo = (int)floorf((po.x + 50.0f) / 0.78125f);
            int iyo = (int)floorf((po.y + 50.0f) / 0.78125f);
            bool v = (ixo >= 0) & (ixo < BEV_W) & (iyo >= 0) & (iyo < BEV_H);
            int row = qg + 8 * tig;
            int gb = v ? ((base + row) / NP_) * HW_ + iyo * BEV_W + ixo : -1;
            g_buf[w][row] = gb;
            if (v) atomicAdd(&g_cnt[gb], 1.0f);
        }
        __syncwarp();

        // Layer 1 -> fp16 A fragments (m16n8k16 layout).
        // A0 = tile rows 0..15 (qg, qg+8), A1 = rows 16..31.
        uint32_t A0[5][4], A1[5][4];
#pragma unroll
        for (int ks = 0; ks < 5; ks++) {
            const int c00 = ks * 16 + 2 * tig;
#pragma unroll
            for (int half = 0; half < 2; half++) {
                const int ca = c00 + 8 * half, cb = ca + 1;
                float wa0 = sW1[ca], wa1 = sW1[C_MID + ca],
                      wa2 = sW1[2 * C_MID + ca], wa3 = sW1[3 * C_MID + ca], ba = sb1[ca];
                float wb0 = sW1[cb], wb1 = sW1[C_MID + cb],
                      wb2 = sW1[2 * C_MID + cb], wb3 = sW1[3 * C_MID + cb], bb = sb1[cb];
#pragma unroll
                for (int j = 0; j < 4; j++) {
                    float va = fmaf(P[j].x, wa0, ba);
                    va = fmaf(P[j].y, wa1, va);
                    va = fmaf(P[j].z, wa2, va);
                    va = fmaf(P[j].w, wa3, va);
                    float vb = fmaf(P[j].x, wb0, bb);
                    vb = fmaf(P[j].y, wb1, vb);
                    vb = fmaf(P[j].z, wb2, vb);
                    vb = fmaf(P[j].w, wb3, vb);
                    uint32_t u = packh2(fmaxf(va, 0.0f), fmaxf(vb, 0.0f));
                    if (j < 2) A0[ks][half * 2 + j] = u;
                    else       A1[ks][half * 2 + (j - 2)] = u;
                }
            }
        }

        const int row0 = (even ? qg : qg + 16);
        const int row1 = row0 + 8;
        const int gv0 = g_buf[w][row0];
        const int gv1 = g_buf[w][row1];

#pragma unroll 1
        for (int ns = 0; ns < 10; ns++) {
            float c0[4] = {0.f, 0.f, 0.f, 0.f};
            float c1[4] = {0.f, 0.f, 0.f, 0.f};
#pragma unroll
            for (int ks = 0; ks < 5; ks++) {
                uint2 bf = *reinterpret_cast<const uint2*>(
                    &sW2F[((ks * 10 + ns) * 32 + lane) * 2]);
                mma_f16(c0, A0[ks], bf.x, bf.y);
                mma_f16(c1, A1[ks], bf.x, bf.y);
            }
            float r0 = __shfl_xor_sync(0xffffffffu, even ? c1[0] : c0[0], 1);
            float r1 = __shfl_xor_sync(0xffffffffu, even ? c1[1] : c0[1], 1);
            float r2 = __shfl_xor_sync(0xffffffffu, even ? c1[2] : c0[2], 1);
            float r3 = __shfl_xor_sync(0xffffffffu, even ? c1[3] : c0[3], 1);
            float k0 = even ? c0[0] : c1[0], k1 = even ? c0[1] : c1[1];
            float k2 = even ? c0[2] : c1[2], k3 = even ? c0[3] : c1[3];
            float x0 = even ? k0 : r0, x1 = even ? k1 : r1;
            float x2 = even ? r0 : k0, x3 = even ? r1 : k1;
            float y0 = even ? k2 : r2, y1 = even ? k3 : r3;
            float y2 = even ? r2 : k2, y3 = even ? r3 : k3;
            const int colbase = ns * 8 + (even ? 2 * tig : 2 * tig - 2);
            float4 bb = *reinterpret_cast<const float4*>(&sb2[colbase]);
            float e0 = fmaxf(x0 + bb.x, 0.0f), e1 = fmaxf(x1 + bb.y, 0.0f);
            float e2 = fmaxf(x2 + bb.z, 0.0f), e3 = fmaxf(x3 + bb.w, 0.0f);
            float f0 = fmaxf(y0 + bb.x, 0.0f), f1 = fmaxf(y1 + bb.y, 0.0f);
            float f2v = fmaxf(y2 + bb.z, 0.0f), f3 = fmaxf(y3 + bb.w, 0.0f);
            if (gv0 >= 0) {
                asm volatile("red.global.add.v4.f32 [%0], {%1, %2, %3, %4};"
                             :: "l"(&g_sums[(size_t)gv0 * C_MID + colbase]),
                                "f"(e0), "f"(e1), "f"(e2), "f"(e3) : "memory");
            }
            if (gv1 >= 0) {
                asm volatile("red.global.add.v4.f32 [%0], {%1, %2, %3, %4};"
                             :: "l"(&g_sums[(size_t)gv1 * C_MID + colbase]),
                                "f"(f0), "f"(f1), "f"(f2v), "f"(f3) : "memory");
            }
        }
        __syncwarp();
    }
}

// ---------------------------------------------------------------------------
// Kernel 2: mean + 1x1 conv + BN + relu via tensor cores (unchanged, ~22us).
// ---------------------------------------------------------------------------
__global__ __launch_bounds__(128)
void bev_mma_kernel(const float* __restrict__ Wp, const float* __restrict__ bp,
                    const float* __restrict__ gamma, const float* __restrict__ beta,
                    const float* __restrict__ rmean, const float* __restrict__ rvar,
                    float* __restrict__ out) {
    __shared__ uint32_t sWpF[10 * 16 * 32 * 2];  // 40 KB
    __shared__ float sScale[C_OUT];
    __shared__ float sShift[C_OUT];

    const int tid = threadIdx.x;
    const int w = tid >> 5;
    const int lane = tid & 31;
    const int qg = lane >> 2;
    const int tig = lane & 3;

    for (int e = tid; e < 10240; e += 128) {
        int pair = e & 1;
        int L = (e >> 1) & 31;
        int idx = e >> 6;
        int ns = idx & 15, ks = idx >> 4;
        int k = ks * 8 + (L & 3) + pair * 4;
        int n = ns * 8 + (L >> 2);
        sWpF[e] = f2tf32(Wp[k * C_OUT + n]);
    }
    if (tid < C_OUT) {
        float sc = gamma[tid] * rsqrtf(rvar[tid] + 1e-5f);
        sScale[tid] = sc;
        sShift[tid] = beta[tid] + (bp[tid] - rmean[tid]) * sc;
    }
    __syncthreads();

#pragma unroll 1
    for (int t = 0; t < BEV_TPW; t++) {
        const int tile = (blockIdx.x * 4 + w) * BEV_TPW + t;
        const int tb = tile * 16;

        float cnt0 = g_cnt[tb + qg];
        float cnt1 = g_cnt[tb + qg + 8];
        float inv0 = 1.0f / fmaxf(cnt0, 1.0f);
        float inv1 = 1.0f / fmaxf(cnt1, 1.0f);
        const float* p0 = &g_sums[(size_t)(tb + qg) * C_MID];
        const float* p1 = &g_sums[(size_t)(tb + qg + 8) * C_MID];

        uint32_t A[10][4];
#pragma unroll
        for (int ks = 0; ks < 10; ks++) {
            const int c0 = ks * 8 + tig, c1 = c0 + 4;
            A[ks][0] = f2tf32(p0[c0] * inv0);
            A[ks][1] = f2tf32(p1[c0] * inv1);
            A[ks][2] = f2tf32(p0[c1] * inv0);
            A[ks][3] = f2tf32(p1[c1] * inv1);
        }
        __syncwarp();
        float4* zs = reinterpret_cast<float4*>(&g_sums[(size_t)tb * C_MID]);
#pragma unroll
        for (int j = 0; j < 10; j++)
            zs[lane + 32 * j] = make_float4(0.f, 0.f, 0.f, 0.f);
        if (lane < 16) g_cnt[tb + lane] = 0.0f;

        const int b = tb / HW_;
        const int rem = tb % HW_;
        float* outb = out + (size_t)b * C_OUT * HW_ + rem;

#pragma unroll 1
        for (int ns = 0; ns < 16; ns++) {
            float c[4] = {0.f, 0.f, 0.f, 0.f};
#pragma unroll
            for (int ks = 0; ks < 10; ks++) {
                uint2 bf = *reinterpret_cast<const uint2*>(
                    &sWpF[((ks * 16 + ns) * 32 + lane) * 2]);
                mma_tf32(c, A[ks], bf.x, bf.y);
            }
            const int col0 = ns * 8 + 2 * tig;
            float2 sc = *reinterpret_cast<const float2*>(&sScale[col0]);
            float2 sh = *reinterpret_cast<const float2*>(&sShift[col0]);
            outb[(size_t)col0 * HW_ + qg]           = fmaxf(fmaf(c[0], sc.x, sh.x), 0.0f);
            outb[(size_t)(col0 + 1) * HW_ + qg]     = fmaxf(fmaf(c[1], sc.y, sh.y), 0.0f);
            outb[(size_t)col0 * HW_ + qg + 8]       = fmaxf(fmaf(c[2], sc.x, sh.x), 0.0f);
            outb[(size_t)(col0 + 1) * HW_ + qg + 8] = fmaxf(fmaf(c[3], sc.y, sh.y), 0.0f);
        }
        __syncwarp();
    }
}

__global__ void probe_kernel() {}

// ---------------------------------------------------------------------------
extern "C" void kernel_launch(void* const* d_in, const int* in_sizes, int n_in,
                              void* d_out, int out_size) {
    const float4* pts   = (const float4*)d_in[0];
    const float*  W1    = (const float*)d_in[1];
    const float*  b1    = (const float*)d_in[2];
    const float*  W2    = (const float*)d_in[3];
    const float*  b2    = (const float*)d_in[4];
    const float*  Wp    = (const float*)d_in[5];
    const float*  bp    = (const float*)d_in[6];
    const float*  gamma = (const float*)d_in[7];
    const float*  beta  = (const float*)d_in[8];
    const float*  rmean = (const float*)d_in[9];
    const float*  rvar  = (const float*)d_in[10];
    float* out = (float*)d_out;

    point_mma_kernel<<<POINT_GRID, 128>>>(pts, W1, b1, W2, b2);
    bev_mma_kernel<<<BEV_GRID, 128>>>(Wp, bp, gamma, beta, rmean, rvar, out);
    probe_kernel<<<1, 1>>>();
}

// round 9
// speedup vs baseline: 1.1435x; 1.0175x over previous
#include <cuda_runtime.h>
#include <cstdint>

#define BEV_H 128
#define BEV_W 128
#define HW_ (BEV_H * BEV_W)
#define C_MID 80
#define C_OUT 128
#define B_ 4
#define NP_ 200000
#define TOTAL_PTS (B_ * NP_)

#define WARPS_PER_CTA 4
#define TILES_PER_WARP 5
#define POINT_GRID (TOTAL_PTS / (32 * WARPS_PER_CTA * TILES_PER_WARP))  // 1250

#define BEV_TILES (B_ * HW_ / 16)
#define BEV_TPW 4
#define BEV_GRID (BEV_TILES / (4 * BEV_TPW))   // 256

// Scratch (zero-init at load; bev kernel re-zeroes what it consumes).
__device__ float g_sums[(size_t)B_ * HW_ * C_MID];  // ~21 MB
__device__ float g_cnt[B_ * HW_];

// ---------------------------------------------------------------------------
// helpers
// ---------------------------------------------------------------------------
__device__ __forceinline__ uint32_t f2tf32(float x) {
    uint32_t u;
    asm("cvt.rna.tf32.f32 %0, %1;" : "=r"(u) : "f"(x));
    return u;
}
__device__ __forceinline__ uint32_t packh2(float lo, float hi) {
    uint32_t r;  // cvt.f16x2: first operand -> high half, second -> low half
    asm("cvt.rn.f16x2.f32 %0, %1, %2;" : "=r"(r) : "f"(hi), "f"(lo));
    return r;
}
// m16n8k16 row.col f32.f16.f16.f32
__device__ __forceinline__ void mma_f16(float* c, const uint32_t* a,
                                        uint32_t b0, uint32_t b1) {
    asm("mma.sync.aligned.m16n8k16.row.col.f32.f16.f16.f32 "
        "{%0,%1,%2,%3}, {%4,%5,%6,%7}, {%8,%9}, {%0,%1,%2,%3};"
        : "+f"(c[0]), "+f"(c[1]), "+f"(c[2]), "+f"(c[3])
        : "r"(a[0]), "r"(a[1]), "r"(a[2]), "r"(a[3]), "r"(b0), "r"(b1));
}
// m16n8k8 tf32 (bev kernel)
__device__ __forceinline__ void mma_tf32(float* c, const uint32_t* a,
                                         uint32_t b0, uint32_t b1) {
    asm("mma.sync.aligned.m16n8k8.row.col.f32.tf32.tf32.f32 "
        "{%0,%1,%2,%3}, {%4,%5,%6,%7}, {%8,%9}, {%0,%1,%2,%3};"
        : "+f"(c[0]), "+f"(c[1]), "+f"(c[2]), "+f"(c[3])
        : "r"(a[0]), "r"(a[1]), "r"(a[2]), "r"(a[3]), "r"(b0), "r"(b1));
}
__device__ __forceinline__ void red_v2(float* addr, float a, float b) {
    asm volatile("red.global.add.v2.f32 [%0], {%1, %2};"
                 :: "l"(addr), "f"(a), "f"(b) : "memory");
}

// ---------------------------------------------------------------------------
// Kernel 1: per-point MLP via fp16 tensor cores.
// Epilogue: each lane scatters its own C-fragment rows directly with
// predicated red.v2 (no shuffle-exchange, no smem staging).
// ---------------------------------------------------------------------------
__global__ __launch_bounds__(128, 6)
void point_mma_kernel(const float4* __restrict__ pts,
                      const float* __restrict__ W1, const float* __restrict__ b1,
                      const float* __restrict__ W2, const float* __restrict__ b2) {
    __shared__ uint32_t sW2F[5 * 10 * 32 * 2];   // fp16 b-frags, 12.8 KB
    __shared__ float sW1[4 * C_MID];
    __shared__ float sb1[C_MID];
    __shared__ __align__(8) float sb2[C_MID];

    const int tid = threadIdx.x;
    const int w = tid >> 5;
    const int lane = tid & 31;
    const int qg = lane >> 2;
    const int tig = lane & 3;

    for (int i = tid; i < 4 * C_MID; i += 128) sW1[i] = W1[i];
    for (int i = tid; i < C_MID; i += 128) { sb1[i] = b1[i]; sb2[i] = b2[i]; }
    // fp16 B fragments: entry[(ks*10+ns)*32+L][reg] packs
    // W2[k0][n], W2[k0+1][n], k0 = 16ks + 2*(L&3) + 8*reg, n = 8ns + (L>>2)
    for (int e = tid; e < 3200; e += 128) {
        int reg = e & 1;
        int L = (e >> 1) & 31;
        int idx = e >> 6;
        int ns = idx % 10, ks = idx / 10;
        int k0 = ks * 16 + 2 * (L & 3) + reg * 8;
        int n = ns * 8 + (L >> 2);
        sW2F[e] = packh2(W2[k0 * C_MID + n], W2[(k0 + 1) * C_MID + n]);
    }
    __syncthreads();

    for (int t = 0; t < TILES_PER_WARP; t++) {
        const int tile = (blockIdx.x * WARPS_PER_CTA + w) * TILES_PER_WARP + t;
        const int base = tile * 32;

        // rows qg + 8j (each row loaded by the 4 lanes of the quad: broadcast)
        float4 P[4];
#pragma unroll
        for (int j = 0; j < 4; j++) P[j] = pts[base + qg + 8 * j];

        // This lane owns tile row (qg + 8*tig) for bucket bookkeeping.
        int myg;
        {
            float4 po = P[tig];
            int ixo = (int)floorf((po.x + 50.0f) / 0.78125f);
            int iyo = (int)floorf((po.y + 50.0f) / 0.78125f);
            bool v = (ixo >= 0) & (ixo < BEV_W) & (iyo >= 0) & (iyo < BEV_H);
            int row = qg + 8 * tig;
            myg = v ? ((base + row) / NP_) * HW_ + iyo * BEV_W + ixo : -1;
            if (v) atomicAdd(&g_cnt[myg], 1.0f);
        }
        // g for the 4 rows this lane's C fragments cover: rows qg + 8j,
        // owned by lane ((qg&7)<<2) | j  (row r owner: ((r&7)<<2)|(r>>3)).
        long gv[4];
#pragma unroll
        for (int j = 0; j < 4; j++)
            gv[j] = (long)__shfl_sync(0xffffffffu, myg, (qg << 2) | j);

        // Layer 1 -> fp16 A fragments (m16n8k16 layout).
        uint32_t A0[5][4], A1[5][4];
#pragma unroll
        for (int ks = 0; ks < 5; ks++) {
            const int c00 = ks * 16 + 2 * tig;
#pragma unroll
            for (int half = 0; half < 2; half++) {
                const int ca = c00 + 8 * half, cb = ca + 1;
                float wa0 = sW1[ca], wa1 = sW1[C_MID + ca],
                      wa2 = sW1[2 * C_MID + ca], wa3 = sW1[3 * C_MID + ca], ba = sb1[ca];
                float wb0 = sW1[cb], wb1 = sW1[C_MID + cb],
                      wb2 = sW1[2 * C_MID + cb], wb3 = sW1[3 * C_MID + cb], bb = sb1[cb];
#pragma unroll
                for (int j = 0; j < 4; j++) {
                    float va = fmaf(P[j].x, wa0, ba);
                    va = fmaf(P[j].y, wa1, va);
                    va = fmaf(P[j].z, wa2, va);
                    va = fmaf(P[j].w, wa3, va);
                    float vb = fmaf(P[j].x, wb0, bb);
                    vb = fmaf(P[j].y, wb1, vb);
                    vb = fmaf(P[j].z, wb2, vb);
                    vb = fmaf(P[j].w, wb3, vb);
                    uint32_t u = packh2(fmaxf(va, 0.0f), fmaxf(vb, 0.0f));
                    if (j < 2) A0[ks][half * 2 + j] = u;
                    else       A1[ks][half * 2 + (j - 2)] = u;
                }
            }
        }

#pragma unroll 1
        for (int ns = 0; ns < 10; ns++) {
            float c0[4] = {0.f, 0.f, 0.f, 0.f};
            float c1[4] = {0.f, 0.f, 0.f, 0.f};
#pragma unroll
            for (int ks = 0; ks < 5; ks++) {
                uint2 bf = *reinterpret_cast<const uint2*>(
                    &sW2F[((ks * 10 + ns) * 32 + lane) * 2]);
                mma_f16(c0, A0[ks], bf.x, bf.y);
                mma_f16(c1, A1[ks], bf.x, bf.y);
            }
            const int col = ns * 8 + 2 * tig;
            float2 bb = *reinterpret_cast<const float2*>(&sb2[col]);
            // row qg: c0[0..1]; qg+8: c0[2..3]; qg+16: c1[0..1]; qg+24: c1[2..3]
            if (gv[0] >= 0)
                red_v2(&g_sums[gv[0] * C_MID + col],
                       fmaxf(c0[0] + bb.x, 0.0f), fmaxf(c0[1] + bb.y, 0.0f));
            if (gv[1] >= 0)
                red_v2(&g_sums[gv[1] * C_MID + col],
                       fmaxf(c0[2] + bb.x, 0.0f), fmaxf(c0[3] + bb.y, 0.0f));
            if (gv[2] >= 0)
                red_v2(&g_sums[gv[2] * C_MID + col],
                       fmaxf(c1[0] + bb.x, 0.0f), fmaxf(c1[1] + bb.y, 0.0f));
            if (gv[3] >= 0)
                red_v2(&g_sums[gv[3] * C_MID + col],
                       fmaxf(c1[2] + bb.x, 0.0f), fmaxf(c1[3] + bb.y, 0.0f));
        }
    }
}

// ---------------------------------------------------------------------------
// Kernel 2: mean + 1x1 conv + BN + relu via tensor cores (unchanged, ~22us).
// ---------------------------------------------------------------------------
__global__ __launch_bounds__(128)
void bev_mma_kernel(const float* __restrict__ Wp, const float* __restrict__ bp,
                    const float* __restrict__ gamma, const float* __restrict__ beta,
                    const float* __restrict__ rmean, const float* __restrict__ rvar,
                    float* __restrict__ out) {
    __shared__ uint32_t sWpF[10 * 16 * 32 * 2];  // 40 KB
    __shared__ float sScale[C_OUT];
    __shared__ float sShift[C_OUT];

    const int tid = threadIdx.x;
    const int w = tid >> 5;
    const int lane = tid & 31;
    const int qg = lane >> 2;
    const int tig = lane & 3;

    for (int e = tid; e < 10240; e += 128) {
        int pair = e & 1;
        int L = (e >> 1) & 31;
        int idx = e >> 6;
        int ns = idx & 15, ks = idx >> 4;
        int k = ks * 8 + (L & 3) + pair * 4;
        int n = ns * 8 + (L >> 2);
        sWpF[e] = f2tf32(Wp[k * C_OUT + n]);
    }
    if (tid < C_OUT) {
        float sc = gamma[tid] * rsqrtf(rvar[tid] + 1e-5f);
        sScale[tid] = sc;
        sShift[tid] = beta[tid] + (bp[tid] - rmean[tid]) * sc;
    }
    __syncthreads();

#pragma unroll 1
    for (int t = 0; t < BEV_TPW; t++) {
        const int tile = (blockIdx.x * 4 + w) * BEV_TPW + t;
        const int tb = tile * 16;

        float cnt0 = g_cnt[tb + qg];
        float cnt1 = g_cnt[tb + qg + 8];
        float inv0 = 1.0f / fmaxf(cnt0, 1.0f);
        float inv1 = 1.0f / fmaxf(cnt1, 1.0f);
        const float* p0 = &g_sums[(size_t)(tb + qg) * C_MID];
        const float* p1 = &g_sums[(size_t)(tb + qg + 8) * C_MID];

        uint32_t A[10][4];
#pragma unroll
        for (int ks = 0; ks < 10; ks++) {
            const int c0 = ks * 8 + tig, c1 = c0 + 4;
            A[ks][0] = f2tf32(p0[c0] * inv0);
            A[ks][1] = f2tf32(p1[c0] * inv1);
            A[ks][2] = f2tf32(p0[c1] * inv0);
            A[ks][3] = f2tf32(p1[c1] * inv1);
        }
        __syncwarp();
        float4* zs = reinterpret_cast<float4*>(&g_sums[(size_t)tb * C_MID]);
#pragma unroll
        for (int j = 0; j < 10; j++)
            zs[lane + 32 * j] = make_float4(0.f, 0.f, 0.f, 0.f);
        if (lane < 16) g_cnt[tb + lane] = 0.0f;

        const int b = tb / HW_;
        const int rem = tb % HW_;
        float* outb = out + (size_t)b * C_OUT * HW_ + rem;

#pragma unroll 1
        for (int ns = 0; ns < 16; ns++) {
            float c[4] = {0.f, 0.f, 0.f, 0.f};
#pragma unroll
            for (int ks = 0; ks < 10; ks++) {
                uint2 bf = *reinterpret_cast<const uint2*>(
                    &sWpF[((ks * 16 + ns) * 32 + lane) * 2]);
                mma_tf32(c, A[ks], bf.x, bf.y);
            }
            const int col0 = ns * 8 + 2 * tig;
            float2 sc = *reinterpret_cast<const float2*>(&sScale[col0]);
            float2 sh = *reinterpret_cast<const float2*>(&sShift[col0]);
            outb[(size_t)col0 * HW_ + qg]           = fmaxf(fmaf(c[0], sc.x, sh.x), 0.0f);
            outb[(size_t)(col0 + 1) * HW_ + qg]     = fmaxf(fmaf(c[1], sc.y, sh.y), 0.0f);
            outb[(size_t)col0 * HW_ + qg + 8]       = fmaxf(fmaf(c[2], sc.x, sh.x), 0.0f);
            outb[(size_t)(col0 + 1) * HW_ + qg + 8] = fmaxf(fmaf(c[3], sc.y, sh.y), 0.0f);
        }
        __syncwarp();
    }
}

__global__ void probe_kernel() {}

// ---------------------------------------------------------------------------
extern "C" void kernel_launch(void* const* d_in, const int* in_sizes, int n_in,
                              void* d_out, int out_size) {
    const float4* pts   = (const float4*)d_in[0];
    const float*  W1    = (const float*)d_in[1];
    const float*  b1    = (const float*)d_in[2];
    const float*  W2    = (const float*)d_in[3];
    const float*  b2    = (const float*)d_in[4];
    const float*  Wp    = (const float*)d_in[5];
    const float*  bp    = (const float*)d_in[6];
    const float*  gamma = (const float*)d_in[7];
    const float*  beta  = (const float*)d_in[8];
    const float*  rmean = (const float*)d_in[9];
    const float*  rvar  = (const float*)d_in[10];
    float* out = (float*)d_out;

    point_mma_kernel<<<POINT_GRID, 128>>>(pts, W1, b1, W2, b2);
    bev_mma_kernel<<<BEV_GRID, 128>>>(Wp, bp, gamma, beta, rmean, rvar, out);
    probe_kernel<<<1, 1>>>();
}